// round 2
// baseline (speedup 1.0000x reference)
#include <cuda_runtime.h>
#include <cstdint>

#define BB 8
#define CC 3
#define NN 4096
#define KK 16
#define THREADS 128
#define SLOTS 24

// smem: xs,ys,zs,ss (4*4096 floats = 64KB) + sd/si collect lists (SLOTS*128*8B = 24KB)
#define SMEM_BYTES (4 * NN * 4 + SLOTS * THREADS * 8)

// Deterministic distance: identical fp ops in pass 1 and pass 2 (IEEE -> identical bits).
// d = sq_q + sq_m - 2*inner  (matches reference formula; -2*inner via exact fma)
__device__ __forceinline__ float distq(float xq, float yq, float zq, float sq,
                                       float xm, float ym, float zm, float sm) {
    float inner = xq * xm;
    inner = fmaf(yq, ym, inner);
    inner = fmaf(zq, zm, inner);
    return fmaf(-2.0f, inner, sq + sm);
}

// Insert d into ascending sorted v[16] (values only). Pure min/max shift, branch-free.
__device__ __forceinline__ void insert16(float v[16], float d) {
#pragma unroll
    for (int j = 15; j >= 1; --j)
        v[j] = fminf(v[j], fmaxf(v[j - 1], d));
    v[0] = fminf(v[0], d);
}

extern __shared__ char smem_raw[];

__global__ void __launch_bounds__(THREADS, 2)
knn_edge_kernel(const float* __restrict__ cloud, float* __restrict__ out) {
    float* xs = (float*)smem_raw;
    float* ys = xs + NN;
    float* zs = ys + NN;
    float* ss = zs + NN;
    float* sd = ss + NN;                       // [SLOTS][THREADS] collected dists
    int*   si = (int*)(sd + SLOTS * THREADS);  // [SLOTS][THREADS] collected idx

    const int tid  = threadIdx.x;
    const int b    = blockIdx.x >> 5;       // 32 tiles per batch
    const int tile = blockIdx.x & 31;
    const int q    = tile * THREADS + tid;  // this thread's query point

    // ---- Load batch cloud to SMEM (SoA) ----
    const float4* cb4 = (const float4*)(cloud + (size_t)b * CC * NN);
    float4* xs4 = (float4*)xs; float4* ys4 = (float4*)ys;
    float4* zs4 = (float4*)zs; float4* ss4 = (float4*)ss;
    for (int i = tid; i < NN / 4; i += THREADS) {
        xs4[i] = cb4[i];
        ys4[i] = cb4[NN / 4 + i];
        zs4[i] = cb4[2 * (NN / 4) + i];
    }
    __syncthreads();
    for (int i = tid; i < NN / 4; i += THREADS) {
        float4 X = xs4[i], Y = ys4[i], Z = zs4[i], S;
        S.x = fmaf(X.x, X.x, fmaf(Y.x, Y.x, Z.x * Z.x));
        S.y = fmaf(X.y, X.y, fmaf(Y.y, Y.y, Z.y * Z.y));
        S.z = fmaf(X.z, X.z, fmaf(Y.z, Y.z, Z.z * Z.z));
        S.w = fmaf(X.w, X.w, fmaf(Y.w, Y.w, Z.w * Z.w));
        ss4[i] = S;
    }
    __syncthreads();

    const float xq = xs[q], yq = ys[q], zq = zs[q], sq = ss[q];

    // ---- Pass 1: values-only top-16 -> exact 16th-smallest threshold T ----
    float v[16];
#pragma unroll
    for (int j = 0; j < 16; ++j) v[j] = 3.4e38f;

    for (int m = 0; m < NN; m += 4) {
        float4 X = xs4[m >> 2], Y = ys4[m >> 2], Z = zs4[m >> 2], S = ss4[m >> 2];
        float d0 = distq(xq, yq, zq, sq, X.x, Y.x, Z.x, S.x);
        float d1 = distq(xq, yq, zq, sq, X.y, Y.y, Z.y, S.y);
        float d2 = distq(xq, yq, zq, sq, X.z, Y.z, Z.z, S.z);
        float d3 = distq(xq, yq, zq, sq, X.w, Y.w, Z.w, S.w);
        float mn = fminf(fminf(d0, d1), fminf(d2, d3));
        if (mn < v[15]) {
            if (d0 < v[15]) insert16(v, d0);
            if (d1 < v[15]) insert16(v, d1);
            if (d2 < v[15]) insert16(v, d2);
            if (d3 < v[15]) insert16(v, d3);
        }
    }
    const float T = v[15];  // exact 16th smallest distance (with multiplicity)

    // ---- Pass 2: collect all d <= T (bitwise-identical recompute) ----
    int cnt = 0;
    for (int m = 0; m < NN; m += 4) {
        float4 X = xs4[m >> 2], Y = ys4[m >> 2], Z = zs4[m >> 2], S = ss4[m >> 2];
        float d0 = distq(xq, yq, zq, sq, X.x, Y.x, Z.x, S.x);
        float d1 = distq(xq, yq, zq, sq, X.y, Y.y, Z.y, S.y);
        float d2 = distq(xq, yq, zq, sq, X.z, Y.z, Z.z, S.z);
        float d3 = distq(xq, yq, zq, sq, X.w, Y.w, Z.w, S.w);
        float mn = fminf(fminf(d0, d1), fminf(d2, d3));
        if (mn <= T) {
            if (d0 <= T && cnt < SLOTS) { sd[cnt * THREADS + tid] = d0; si[cnt * THREADS + tid] = m;     ++cnt; }
            if (d1 <= T && cnt < SLOTS) { sd[cnt * THREADS + tid] = d1; si[cnt * THREADS + tid] = m + 1; ++cnt; }
            if (d2 <= T && cnt < SLOTS) { sd[cnt * THREADS + tid] = d2; si[cnt * THREADS + tid] = m + 2; ++cnt; }
            if (d3 <= T && cnt < SLOTS) { sd[cnt * THREADS + tid] = d3; si[cnt * THREADS + tid] = m + 3; ++cnt; }
        }
    }

    // ---- Tie-exact compaction to 16 (all d<T, then d==T in index order) ----
    int c1 = 0;
    for (int s = 0; s < cnt; ++s) c1 += (sd[s * THREADS + tid] < T) ? 1 : 0;
    int need_eq = 16 - c1;
    int pos = 0, eq = 0;
    for (int s = 0; s < cnt; ++s) {
        float d = sd[s * THREADS + tid];
        int   ii = si[s * THREADS + tid];
        bool isEq = (d == T);
        bool take = (!isEq) || (eq < need_eq);
        if (take && pos < 16) {
            sd[pos * THREADS + tid] = d;
            si[pos * THREADS + tid] = ii;
            ++pos;
            if (isEq) ++eq;
        }
    }
    // defensive pad (unreachable if recompute is bit-identical, which it is)
    while (pos < 16) { sd[pos * THREADS + tid] = T; si[pos * THREADS + tid] = q; ++pos; }

    float rd[16]; int ri[16];
#pragma unroll
    for (int k = 0; k < 16; ++k) {
        rd[k] = sd[k * THREADS + tid];
        ri[k] = si[k * THREADS + tid];
    }

    // ---- Bitonic sort 16 by (dist asc, idx asc) == lax.top_k order ----
#pragma unroll
    for (int kk = 2; kk <= 16; kk <<= 1) {
#pragma unroll
        for (int jj = kk >> 1; jj > 0; jj >>= 1) {
#pragma unroll
            for (int i = 0; i < 16; ++i) {
                int l = i ^ jj;
                if (l > i) {
                    bool asc = ((i & kk) == 0);
                    bool lLess = (rd[l] < rd[i]) || (rd[l] == rd[i] && ri[l] < ri[i]);
                    if (lLess == asc) {
                        float td = rd[i]; rd[i] = rd[l]; rd[l] = td;
                        int   ti = ri[i]; ri[i] = ri[l]; ri[l] = ti;
                    }
                }
            }
        }
    }

    // ---- Emit edge features: out[b][c][q][k] ----
    float nx[16], ny[16], nz[16];
#pragma unroll
    for (int k = 0; k < 16; ++k) {
        int ii = ri[k];
        nx[k] = xs[ii] - xq;
        ny[k] = ys[ii] - yq;
        nz[k] = zs[ii] - zq;
    }

    size_t base = (((size_t)b * 6) * NN + q) * KK;  // c stride = NN*KK
    // central (c = 0..2): constant across k
    {
        float cvals[3] = {xq, yq, zq};
#pragma unroll
        for (int c = 0; c < 3; ++c) {
            float4 vv = make_float4(cvals[c], cvals[c], cvals[c], cvals[c]);
            float4* op = (float4*)(out + base + (size_t)c * NN * KK);
            op[0] = vv; op[1] = vv; op[2] = vv; op[3] = vv;
        }
    }
    // neighbor - central (c = 3..5)
    {
        float4* op = (float4*)(out + base + (size_t)3 * NN * KK);
        op[0] = make_float4(nx[0], nx[1], nx[2], nx[3]);
        op[1] = make_float4(nx[4], nx[5], nx[6], nx[7]);
        op[2] = make_float4(nx[8], nx[9], nx[10], nx[11]);
        op[3] = make_float4(nx[12], nx[13], nx[14], nx[15]);
        op = (float4*)(out + base + (size_t)4 * NN * KK);
        op[0] = make_float4(ny[0], ny[1], ny[2], ny[3]);
        op[1] = make_float4(ny[4], ny[5], ny[6], ny[7]);
        op[2] = make_float4(ny[8], ny[9], ny[10], ny[11]);
        op[3] = make_float4(ny[12], ny[13], ny[14], ny[15]);
        op = (float4*)(out + base + (size_t)5 * NN * KK);
        op[0] = make_float4(nz[0], nz[1], nz[2], nz[3]);
        op[1] = make_float4(nz[4], nz[5], nz[6], nz[7]);
        op[2] = make_float4(nz[8], nz[9], nz[10], nz[11]);
        op[3] = make_float4(nz[12], nz[13], nz[14], nz[15]);
    }
}

extern "C" void kernel_launch(void* const* d_in, const int* in_sizes, int n_in,
                              void* d_out, int out_size) {
    const float* cloud = (const float*)d_in[0];
    float* out = (float*)d_out;

    // Unconditional (no static guards): host-side attribute set, not a stream op,
    // so it is graph-capture-safe and idempotent.
    cudaFuncSetAttribute(knn_edge_kernel,
                         cudaFuncAttributeMaxDynamicSharedMemorySize, SMEM_BYTES);

    dim3 grid(BB * (NN / THREADS));  // 8 * 32 = 256 blocks
    dim3 block(THREADS);
    knn_edge_kernel<<<grid, block, SMEM_BYTES>>>(cloud, out);
}

// round 3
// speedup vs baseline: 1.4491x; 1.4491x over previous
#include <cuda_runtime.h>
#include <cstdint>

#define BB 8
#define NN 4096
#define HALF 2048
#define KK 16
#define THREADS 256
#define QPB 128          // queries per block
#define SLOTSH 32        // collect slots per half
#define FLTMAX 3.402823466e38f

// smem: xs,ys,zs (3*4096*4 = 48KB) + sd f32[64][128] (32KB) + si u16[64][128] (16KB) + scnt (1KB)
#define SMEM_BYTES ((3 * NN) * 4 + (2 * SLOTSH * QPB) * 4 + (2 * SLOTSH * QPB) * 2 + THREADS * 4)

// ---------------- packed f32x2 helpers ----------------
__device__ __forceinline__ unsigned long long pk2(float v) {
    unsigned long long r;
    asm("mov.b64 %0, {%1, %1};" : "=l"(r) : "f"(v));
    return r;
}
__device__ __forceinline__ unsigned long long mul2_(unsigned long long a, unsigned long long b) {
    unsigned long long r;
    asm("mul.rn.f32x2 %0, %1, %2;" : "=l"(r) : "l"(a), "l"(b));
    return r;
}
__device__ __forceinline__ unsigned long long add2_(unsigned long long a, unsigned long long b) {
    unsigned long long r;
    asm("add.rn.f32x2 %0, %1, %2;" : "=l"(r) : "l"(a), "l"(b));
    return r;
}
__device__ __forceinline__ unsigned long long fma2_(unsigned long long a, unsigned long long b,
                                                    unsigned long long c) {
    unsigned long long r;
    asm("fma.rn.f32x2 %0, %1, %2, %3;" : "=l"(r) : "l"(a), "l"(b), "l"(c));
    return r;
}
__device__ __forceinline__ void unpk2(unsigned long long v, float& lo, float& hi) {
    asm("mov.b64 {%0, %1}, %2;" : "=f"(lo), "=f"(hi) : "l"(v));
}

// Distance for 2 candidates, bitwise identical to scalar:
//   sm   = fmaf(x,x, fmaf(y,y, z*z))
//   in   = fmaf(z,zq, fmaf(y,yq, x*xq))
//   d    = fmaf(-2, in, sq + sm)
__device__ __forceinline__ unsigned long long dist2(
    unsigned long long x2, unsigned long long y2, unsigned long long z2,
    unsigned long long xq2, unsigned long long yq2, unsigned long long zq2,
    unsigned long long sq2, unsigned long long n2) {
    unsigned long long sm = fma2_(x2, x2, fma2_(y2, y2, mul2_(z2, z2)));
    unsigned long long in = fma2_(z2, zq2, fma2_(y2, yq2, mul2_(x2, xq2)));
    return fma2_(n2, in, add2_(sq2, sm));
}

// Values-only sorted-16 insert (branch-free min/max shift)
__device__ __forceinline__ void insert16(float v[16], float d) {
#pragma unroll
    for (int j = 15; j >= 1; --j)
        v[j] = fminf(v[j], fmaxf(v[j - 1], d));
    v[0] = fminf(v[0], d);
}

// (d, idx) lexicographic pair-insert into sorted 16-list (lax.top_k order)
__device__ __forceinline__ void pins(float rd[16], int ri[16], float d, int i) {
    bool lessLast = (d < rd[15]) || (d == rd[15] && i < ri[15]);
    if (!lessLast) return;
#pragma unroll
    for (int j = 15; j >= 1; --j) {
        bool le = (d < rd[j - 1]) || (d == rd[j - 1] && i < ri[j - 1]);
        bool lj = (d < rd[j]) || (d == rd[j] && i < ri[j]);
        rd[j] = le ? rd[j - 1] : (lj ? d : rd[j]);
        ri[j] = le ? ri[j - 1] : (lj ? i : ri[j]);
    }
    bool l0 = (d < rd[0]) || (d == rd[0] && i < ri[0]);
    if (l0) { rd[0] = d; ri[0] = i; }
}

extern __shared__ char smem_raw[];

__global__ void __launch_bounds__(THREADS, 2)
knn_edge_kernel(const float* __restrict__ cloud, float* __restrict__ out) {
    float* xs = (float*)smem_raw;
    float* ys = xs + NN;
    float* zs = ys + NN;
    float* sd = zs + NN;                                 // [64][128] f32
    unsigned short* si = (unsigned short*)(sd + 2 * SLOTSH * QPB);  // [64][128] u16
    int* scnt = (int*)(si + 2 * SLOTSH * QPB);           // [256]

    const int tid = threadIdx.x;
    const int qc  = tid & (QPB - 1);   // query column 0..127
    const int h   = tid >> 7;          // half 0/1
    const int b    = blockIdx.x >> 5;
    const int tile = blockIdx.x & 31;
    const int q    = tile * QPB + qc;

    // ---- Load batch cloud to SMEM (SoA xyz) ----
    const float4* cb4 = (const float4*)(cloud + (size_t)b * 3 * NN);
    float4* xs4 = (float4*)xs; float4* ys4 = (float4*)ys; float4* zs4 = (float4*)zs;
    for (int i = tid; i < NN / 4; i += THREADS) {
        xs4[i] = cb4[i];
        ys4[i] = cb4[NN / 4 + i];
        zs4[i] = cb4[2 * (NN / 4) + i];
    }
    __syncthreads();

    const float xq = xs[q], yq = ys[q], zq = zs[q];
    const float sq = fmaf(xq, xq, fmaf(yq, yq, zq * zq));

    const unsigned long long xq2 = pk2(xq), yq2 = pk2(yq), zq2 = pk2(zq);
    const unsigned long long sq2 = pk2(sq), n2 = pk2(-2.0f);

    const ulonglong2* xs2 = (const ulonglong2*)xs;
    const ulonglong2* ys2 = (const ulonglong2*)ys;
    const ulonglong2* zs2 = (const ulonglong2*)zs;

    const int mstart = h * HALF;

    // ---- Pass 1: branch-free 16-bucket depth-2 min sketch over this half ----
    float m1[16], m2[16];
#pragma unroll
    for (int t = 0; t < 16; ++t) { m1[t] = FLTMAX; m2[t] = FLTMAX; }

#pragma unroll 1
    for (int it = 0; it < HALF / 16; ++it) {
        const int c0 = mstart + it * 16;
#pragma unroll
        for (int j = 0; j < 4; ++j) {
            const int p = (c0 >> 2) + j;
            ulonglong2 X = xs2[p], Y = ys2[p], Z = zs2[p];
            float d0, d1, d2v, d3;
            unpk2(dist2(X.x, Y.x, Z.x, xq2, yq2, zq2, sq2, n2), d0, d1);
            unpk2(dist2(X.y, Y.y, Z.y, xq2, yq2, zq2, sq2, n2), d2v, d3);
            const int t0 = j * 4;
            m2[t0 + 0] = fminf(m2[t0 + 0], fmaxf(m1[t0 + 0], d0)); m1[t0 + 0] = fminf(m1[t0 + 0], d0);
            m2[t0 + 1] = fminf(m2[t0 + 1], fmaxf(m1[t0 + 1], d1)); m1[t0 + 1] = fminf(m1[t0 + 1], d1);
            m2[t0 + 2] = fminf(m2[t0 + 2], fmaxf(m1[t0 + 2], d2v)); m1[t0 + 2] = fminf(m1[t0 + 2], d2v);
            m2[t0 + 3] = fminf(m2[t0 + 3], fmaxf(m1[t0 + 3], d3)); m1[t0 + 3] = fminf(m1[t0 + 3], d3);
        }
    }

    // T = 16th smallest of the 32 stored values (guaranteed >= exact d16 of this half)
    float v[16];
#pragma unroll
    for (int t = 0; t < 16; ++t) v[t] = FLTMAX;
#pragma unroll
    for (int t = 0; t < 16; ++t) { insert16(v, m1[t]); insert16(v, m2[t]); }
    const float T = v[15];

    // ---- Pass 2: collect all d <= T into shared lists (bitwise-identical recompute) ----
    const int rowbase = h * SLOTSH;
    int cnt = 0;
#pragma unroll 1
    for (int it = 0; it < HALF / 16; ++it) {
        const int c0 = mstart + it * 16;
#pragma unroll
        for (int j = 0; j < 4; ++j) {
            const int p = (c0 >> 2) + j;
            ulonglong2 X = xs2[p], Y = ys2[p], Z = zs2[p];
            float dd[4];
            unpk2(dist2(X.x, Y.x, Z.x, xq2, yq2, zq2, sq2, n2), dd[0], dd[1]);
            unpk2(dist2(X.y, Y.y, Z.y, xq2, yq2, zq2, sq2, n2), dd[2], dd[3]);
#pragma unroll
            for (int k = 0; k < 4; ++k) {
                bool pr = (dd[k] <= T) && (cnt < SLOTSH);
                int row = rowbase + cnt;
                if (pr) {
                    sd[row * QPB + qc] = dd[k];
                    si[row * QPB + qc] = (unsigned short)(c0 + j * 4 + k);
                }
                cnt += pr;
            }
        }
    }

    // ---- Overflow fallback (essentially never taken): exact pair top-16 rescan ----
    if (cnt >= SLOTSH) {
        float rdF[16]; int riF[16];
#pragma unroll
        for (int t = 0; t < 16; ++t) { rdF[t] = FLTMAX; riF[t] = 0; }
        for (int m = mstart; m < mstart + HALF; m += 2) {
            ulonglong2 dummy;
            const int p = m >> 2;
            // scalar recompute (bitwise-identical formula)
            float xm0 = xs[m], ym0 = ys[m], zm0 = zs[m];
            float xm1 = xs[m + 1], ym1 = ys[m + 1], zm1 = zs[m + 1];
            float sm0 = fmaf(xm0, xm0, fmaf(ym0, ym0, zm0 * zm0));
            float in0 = fmaf(zm0, zq, fmaf(ym0, yq, xm0 * xq));
            float d0 = fmaf(-2.0f, in0, sq + sm0);
            float sm1 = fmaf(xm1, xm1, fmaf(ym1, ym1, zm1 * zm1));
            float in1 = fmaf(zm1, zq, fmaf(ym1, yq, xm1 * xq));
            float d1 = fmaf(-2.0f, in1, sq + sm1);
            pins(rdF, riF, d0, m);
            pins(rdF, riF, d1, m + 1);
            (void)dummy; (void)p;
        }
#pragma unroll
        for (int t = 0; t < 16; ++t) {
            sd[(rowbase + t) * QPB + qc] = rdF[t];
            si[(rowbase + t) * QPB + qc] = (unsigned short)riF[t];
        }
        cnt = 16;
    }
    scnt[tid] = cnt;
    __syncthreads();

    // ---- Exact selection over both halves' survivors (threads 0..127) ----
    float rd[16]; int ri[16];
    if (tid < QPB) {
#pragma unroll
        for (int t = 0; t < 16; ++t) { rd[t] = FLTMAX; ri[t] = 0; }
        const int c1 = scnt[tid];
        for (int s = 0; s < c1; ++s)
            pins(rd, ri, sd[s * QPB + tid], (int)si[s * QPB + tid]);
        const int c2 = scnt[QPB + tid];
        for (int s = 0; s < c2; ++s)
            pins(rd, ri, sd[(SLOTSH + s) * QPB + tid], (int)si[(SLOTSH + s) * QPB + tid]);
        // hand off sorted indices to the upper-half partner thread
#pragma unroll
        for (int t = 0; t < 16; ++t)
            si[t * QPB + tid] = (unsigned short)ri[t];
    }
    __syncthreads();

    // ---- Emit edge features: out[b][c][q][k]; split channels across halves ----
    const size_t base = (((size_t)b * 6) * NN + q) * KK;
    if (tid < QPB) {
        // central channels 0..2
        float cvals[3] = {xq, yq, zq};
#pragma unroll
        for (int c = 0; c < 3; ++c) {
            float4 vv = make_float4(cvals[c], cvals[c], cvals[c], cvals[c]);
            float4* op = (float4*)(out + base + (size_t)c * NN * KK);
            op[0] = vv; op[1] = vv; op[2] = vv; op[3] = vv;
        }
        // channel 3: nx
        float nx[16];
#pragma unroll
        for (int k = 0; k < 16; ++k) nx[k] = xs[ri[k]] - xq;
        float4* op = (float4*)(out + base + (size_t)3 * NN * KK);
        op[0] = make_float4(nx[0], nx[1], nx[2], nx[3]);
        op[1] = make_float4(nx[4], nx[5], nx[6], nx[7]);
        op[2] = make_float4(nx[8], nx[9], nx[10], nx[11]);
        op[3] = make_float4(nx[12], nx[13], nx[14], nx[15]);
    } else {
        int rr[16];
#pragma unroll
        for (int k = 0; k < 16; ++k) rr[k] = (int)si[k * QPB + qc];
        float ny[16], nz[16];
#pragma unroll
        for (int k = 0; k < 16; ++k) {
            ny[k] = ys[rr[k]] - yq;
            nz[k] = zs[rr[k]] - zq;
        }
        float4* op = (float4*)(out + base + (size_t)4 * NN * KK);
        op[0] = make_float4(ny[0], ny[1], ny[2], ny[3]);
        op[1] = make_float4(ny[4], ny[5], ny[6], ny[7]);
        op[2] = make_float4(ny[8], ny[9], ny[10], ny[11]);
        op[3] = make_float4(ny[12], ny[13], ny[14], ny[15]);
        op = (float4*)(out + base + (size_t)5 * NN * KK);
        op[0] = make_float4(nz[0], nz[1], nz[2], nz[3]);
        op[1] = make_float4(nz[4], nz[5], nz[6], nz[7]);
        op[2] = make_float4(nz[8], nz[9], nz[10], nz[11]);
        op[3] = make_float4(nz[12], nz[13], nz[14], nz[15]);
    }
}

extern "C" void kernel_launch(void* const* d_in, const int* in_sizes, int n_in,
                              void* d_out, int out_size) {
    const float* cloud = (const float*)d_in[0];
    float* out = (float*)d_out;

    cudaFuncSetAttribute(knn_edge_kernel,
                         cudaFuncAttributeMaxDynamicSharedMemorySize, SMEM_BYTES);

    dim3 grid(BB * (NN / QPB));   // 8 * 32 = 256 blocks
    dim3 block(THREADS);
    knn_edge_kernel<<<grid, block, SMEM_BYTES>>>(cloud, out);
}